// round 6
// baseline (speedup 1.0000x reference)
#include <cuda_runtime.h>
#include <cuda_fp16.h>
#include <stdint.h>

#define N_NODES 50000
#define N_EDGES 800000
#define IN_F    128
#define OUT_F   64

#define CNT_PAD 53248          // 1024 threads * 52 ints, zero-padded

// Scratch (allocation-free rule: __device__ globals)
__device__ __half g_h[(size_t)N_NODES * OUT_F];     // 6.4 MB fp16 h table
__device__ float  g_Wt[IN_F * OUT_F];               // W transposed [k][o]
__device__ __align__(16) int g_cnt[CNT_PAD];        // per-dst in-degree
__device__ int    g_off[N_NODES + 1];               // CSR offsets
__device__ int    g_cursor[N_NODES];                // fill cursors
__device__ int2   g_srcw[N_EDGES];                  // CSR payload: (src, w-bits)

// ---------------------------------------------------------------------------
// Prep: transpose W + zero the degree counters.
// ---------------------------------------------------------------------------
__global__ __launch_bounds__(256) void prep_kernel(const float* __restrict__ W) {
    const int idx = blockIdx.x * 256 + threadIdx.x;
    if (idx < IN_F * OUT_F) {
        int o = idx >> 7;      // /128
        int k = idx & 127;
        g_Wt[k * OUT_F + o] = W[idx];
    }
    if (idx < CNT_PAD) g_cnt[idx] = 0;
}

// ---------------------------------------------------------------------------
// GEMM: h = feat @ W^T + b  (fp32 compute, fp16 store)
// Tile: 64 nodes x 64 outs per block (256 threads), 4x4 per thread.
// Side-job: dst histogram (fire-and-forget REDG, hidden under compute).
// ---------------------------------------------------------------------------
__global__ __launch_bounds__(256) void gemm_kernel(
    const float* __restrict__ feat,
    const float* __restrict__ b,
    const int* __restrict__ edst)
{
    __shared__ float sW[IN_F * OUT_F];   // 32 KB [k][o]
    __shared__ float sF[64 * IN_F];      // 32 KB [n_local][k]

    const int tid = threadIdx.x;
    const int node0 = blockIdx.x * 64;

    // Histogram side-job: 1024 edges per block, 4 per thread
    {
        const int ebase = blockIdx.x * 1024 + tid;
        #pragma unroll
        for (int i = 0; i < 4; i++) {
            int e = ebase + i * 256;
            if (e < N_EDGES) atomicAdd(&g_cnt[edst[e]], 1);
        }
    }

    // Load Wt ([k][o], contiguous)
    {
        const float4* src = (const float4*)g_Wt;
        float4* dst = (float4*)sW;
        #pragma unroll
        for (int i = 0; i < 8; i++) dst[tid + i * 256] = src[tid + i * 256];
    }
    // Load 64 feat rows (float4), zero-pad past N_NODES
    {
        const float4* src = (const float4*)feat;
        float4* dst = (float4*)sF;
        #pragma unroll
        for (int i = 0; i < 8; i++) {
            int idx = tid + i * 256;
            int n   = idx >> 5;
            int node = node0 + n;
            dst[idx] = (node < N_NODES) ? src[(size_t)node * 32 + (idx & 31)]
                                        : make_float4(0.f, 0.f, 0.f, 0.f);
        }
    }
    __syncthreads();

    const int og = tid & 15;
    const int nl = tid >> 4;

    const float4 bv = ((const float4*)b)[og];
    float4 acc0 = bv, acc1 = bv, acc2 = bv, acc3 = bv;

    const float4* f0p = (const float4*)(sF + (nl     ) * IN_F);
    const float4* f1p = (const float4*)(sF + (nl + 16) * IN_F);
    const float4* f2p = (const float4*)(sF + (nl + 32) * IN_F);
    const float4* f3p = (const float4*)(sF + (nl + 48) * IN_F);
    const float4* w4  = (const float4*)sW;

    #pragma unroll
    for (int k4 = 0; k4 < IN_F / 4; k4++) {
        float4 f0 = f0p[k4], f1 = f1p[k4], f2 = f2p[k4], f3 = f3p[k4];
        #pragma unroll
        for (int j = 0; j < 4; j++) {
            const float4 w = w4[(k4 * 4 + j) * 16 + og];
            const float a = (&f0.x)[j], bb = (&f1.x)[j], c = (&f2.x)[j], d = (&f3.x)[j];
            acc0.x = fmaf(a, w.x, acc0.x); acc0.y = fmaf(a, w.y, acc0.y);
            acc0.z = fmaf(a, w.z, acc0.z); acc0.w = fmaf(a, w.w, acc0.w);
            acc1.x = fmaf(bb, w.x, acc1.x); acc1.y = fmaf(bb, w.y, acc1.y);
            acc1.z = fmaf(bb, w.z, acc1.z); acc1.w = fmaf(bb, w.w, acc1.w);
            acc2.x = fmaf(c, w.x, acc2.x); acc2.y = fmaf(c, w.y, acc2.y);
            acc2.z = fmaf(c, w.z, acc2.z); acc2.w = fmaf(c, w.w, acc2.w);
            acc3.x = fmaf(d, w.x, acc3.x); acc3.y = fmaf(d, w.y, acc3.y);
            acc3.z = fmaf(d, w.z, acc3.z); acc3.w = fmaf(d, w.w, acc3.w);
        }
    }

    #pragma unroll
    for (int i = 0; i < 4; i++) {
        const int node = node0 + nl + i * 16;
        if (node < N_NODES) {
            float4 v = (i == 0) ? acc0 : (i == 1) ? acc1 : (i == 2) ? acc2 : acc3;
            __half2 h0 = __floats2half2_rn(v.x, v.y);
            __half2 h1 = __floats2half2_rn(v.z, v.w);
            uint2 pk;
            pk.x = *(const unsigned int*)&h0;
            pk.y = *(const unsigned int*)&h1;
            *(uint2*)(g_h + (size_t)node * OUT_F + og * 4) = pk;
        }
    }
}

// ---------------------------------------------------------------------------
// Scan: exclusive prefix over g_cnt -> g_off (+ g_cursor copy).
// One block, 1024 threads, 52 ints (13 int4) per thread.
// ---------------------------------------------------------------------------
__global__ __launch_bounds__(1024) void scan_kernel() {
    const int tid = threadIdx.x;
    const int4* cnt4 = (const int4*)g_cnt;

    int4 v[13];
    int sum = 0;
    #pragma unroll
    for (int c = 0; c < 13; c++) {
        v[c] = cnt4[tid * 13 + c];
        sum += v[c].x + v[c].y + v[c].z + v[c].w;
    }

    // Hillis-Steele inclusive scan over 1024 thread-sums (double buffer)
    __shared__ int sbuf[2][1024];
    int cur = 0;
    sbuf[0][tid] = sum;
    __syncthreads();
    #pragma unroll
    for (int d = 1; d < 1024; d <<= 1) {
        int val = sbuf[cur][tid];
        if (tid >= d) val += sbuf[cur][tid - d];
        sbuf[cur ^ 1][tid] = val;
        cur ^= 1;
        __syncthreads();
    }
    int running = (tid == 0) ? 0 : sbuf[cur][tid - 1];   // exclusive

    // Write exclusive offsets for my 52 ints
    const int base = tid * 52;
    #pragma unroll
    for (int c = 0; c < 13; c++) {
        int vals[4] = {v[c].x, v[c].y, v[c].z, v[c].w};
        #pragma unroll
        for (int q = 0; q < 4; q++) {
            int idx = base + c * 4 + q;
            if (idx < N_NODES) {
                g_off[idx] = running;
                g_cursor[idx] = running;
            } else if (idx == N_NODES) {
                g_off[N_NODES] = running;   // == N_EDGES
            }
            running += vals[q];
        }
    }
}

// ---------------------------------------------------------------------------
// Fill: place each edge's (src, weight) into its CSR slot.
// ---------------------------------------------------------------------------
__global__ __launch_bounds__(256) void fill_kernel(
    const int* __restrict__ esrc,
    const int* __restrict__ edst,
    const float* __restrict__ ew)
{
    const int e = blockIdx.x * 256 + threadIdx.x;
    if (e >= N_EDGES) return;
    const int d = edst[e];
    const int pos = atomicAdd(&g_cursor[d], 1);
    g_srcw[pos] = make_int2(esrc[e], __float_as_int(ew[e]));
}

// ---------------------------------------------------------------------------
// Gather-reduce: out[d] = sum over in-edges of h[src] * w.  NO atomics.
// One warp per dst node; lane owns 2 output floats (one __half2 of h row).
// ---------------------------------------------------------------------------
__global__ __launch_bounds__(256) void gather_kernel(float* __restrict__ out) {
    const int warp = (blockIdx.x * 256 + threadIdx.x) >> 5;
    const int lane = threadIdx.x & 31;
    if (warp >= N_NODES) return;

    const int start = g_off[warp];
    const int end   = g_off[warp + 1];

    float2 acc = make_float2(0.f, 0.f);

    for (int i = start; i < end; i += 32) {
        int2 meta = (i + lane < end) ? g_srcw[i + lane] : make_int2(0, 0);
        const int n = min(32, end - i);
        for (int j = 0; j < n; j++) {
            const int   s = __shfl_sync(0xffffffff, meta.x, j);
            const float w = __int_as_float(__shfl_sync(0xffffffff, meta.y, j));
            const __half2 hv = *(const __half2*)(g_h + ((size_t)s << 6) + lane * 2);
            const float2 f = __half22float2(hv);
            acc.x = fmaf(f.x, w, acc.x);
            acc.y = fmaf(f.y, w, acc.y);
        }
    }

    *(float2*)(out + ((size_t)warp << 6) + lane * 2) = acc;
}

// ---------------------------------------------------------------------------
extern "C" void kernel_launch(void* const* d_in, const int* in_sizes, int n_in,
                              void* d_out, int out_size) {
    const float* feat = (const float*)d_in[0];
    const int*   esrc = (const int*)d_in[1];   // int32 (JAX x64 disabled)
    const int*   edst = (const int*)d_in[2];
    const float* ew   = (const float*)d_in[3];
    const float* W    = (const float*)d_in[4];
    const float* b    = (const float*)d_in[5];
    float* out = (float*)d_out;

    prep_kernel<<<(CNT_PAD + 255) / 256, 256>>>(W);              // transpose + zero counters

    gemm_kernel<<<(N_NODES + 63) / 64, 256>>>(feat, b, edst);    // + histogram

    scan_kernel<<<1, 1024>>>();

    fill_kernel<<<(N_EDGES + 255) / 256, 256>>>(esrc, edst, ew);

    gather_kernel<<<(N_NODES * 32 + 255) / 256, 256>>>(out);     // warp per node
}

// round 7
// speedup vs baseline: 1.5268x; 1.5268x over previous
#include <cuda_runtime.h>
#include <cuda_fp16.h>
#include <stdint.h>

#define N_NODES 50000
#define N_EDGES 800000
#define IN_F    128
#define OUT_F   64

#define SA_STRIDE 136   // halves per smem row (128 + 8 pad -> conflict-free frags)

// Scratch (allocation-free rule: __device__ globals)
__device__ __half g_h[(size_t)N_NODES * OUT_F];  // 6.4 MB fp16 h table (L2-resident)

// ---------------------------------------------------------------------------
// GEMM: h = feat @ W^T + b  via mma.sync m16n8k16 (fp16 in, fp32 accum).
// Block: 64 nodes x 64 outs, 256 threads (8 warps).
// Warp w: nodes [(w>>1)*16, +16), outs [(w&1)*32, +32) -> 8 ksteps x 4 nchunks.
// W is used as the col-major B operand directly ([o][k] native layout, no
// transpose). Side-job: zero `out` (hidden behind compute).
// ---------------------------------------------------------------------------
__global__ __launch_bounds__(256) void gemm_kernel(
    const float* __restrict__ feat,
    const float* __restrict__ W,
    const float* __restrict__ b,
    float4* __restrict__ out4)
{
    __shared__ __half sA[64 * SA_STRIDE];   // feat tile  [node][k]
    __shared__ __half sB[64 * SA_STRIDE];   // W          [o][k]
    __shared__ float  sBias[OUT_F];

    const int tid = threadIdx.x;
    const int node0 = blockIdx.x * 64;

    // Zero the output (independent side-job)
    {
        const int per_blk = (N_NODES * OUT_F / 4 + gridDim.x - 1) / gridDim.x;
        int base = blockIdx.x * per_blk;
        for (int i = tid; i < per_blk; i += 256) {
            int idx = base + i;
            if (idx < N_NODES * OUT_F / 4)
                out4[idx] = make_float4(0.f, 0.f, 0.f, 0.f);
        }
    }

    if (tid < OUT_F) sBias[tid] = b[tid];

    // Load W [64 x 128] fp32 -> fp16 smem (2048 float4, 8 per thread)
    {
        const float4* src = (const float4*)W;
        #pragma unroll
        for (int i = 0; i < 8; i++) {
            int idx = tid + i * 256;
            int o = idx >> 5, c4 = idx & 31;
            float4 v = src[idx];
            __half2 h01 = __floats2half2_rn(v.x, v.y);
            __half2 h23 = __floats2half2_rn(v.z, v.w);
            uint2 pk;
            pk.x = *(const unsigned int*)&h01;
            pk.y = *(const unsigned int*)&h23;
            *(uint2*)&sB[o * SA_STRIDE + c4 * 4] = pk;
        }
    }
    // Load 64 feat rows fp32 -> fp16 smem, zero-pad past N_NODES
    {
        const float4* src = (const float4*)feat;
        #pragma unroll
        for (int i = 0; i < 8; i++) {
            int idx = tid + i * 256;
            int n = idx >> 5, c4 = idx & 31;
            int node = node0 + n;
            float4 v = (node < N_NODES) ? src[(size_t)node * 32 + c4]
                                        : make_float4(0.f, 0.f, 0.f, 0.f);
            __half2 h01 = __floats2half2_rn(v.x, v.y);
            __half2 h23 = __floats2half2_rn(v.z, v.w);
            uint2 pk;
            pk.x = *(const unsigned int*)&h01;
            pk.y = *(const unsigned int*)&h23;
            *(uint2*)&sA[n * SA_STRIDE + c4 * 4] = pk;
        }
    }
    __syncthreads();

    const int lane = tid & 31;
    const int w    = tid >> 5;
    const int g    = lane >> 2;        // groupID (row within 8)
    const int t    = lane & 3;         // thread-in-group (col pair)
    const int mrow = (w >> 1) * 16;    // local node base
    const int nbase = (w & 1) * 32;    // out-column base

    float c[4][4] = {};   // 4 n-chunks x m16n8 fragment (zeros; bias added later)

    #pragma unroll
    for (int ks = 0; ks < 8; ks++) {
        const int k0 = ks * 16;
        const uint32_t a0 = *(const uint32_t*)&sA[(mrow + g    ) * SA_STRIDE + k0 + 2 * t];
        const uint32_t a1 = *(const uint32_t*)&sA[(mrow + g + 8) * SA_STRIDE + k0 + 2 * t];
        const uint32_t a2 = *(const uint32_t*)&sA[(mrow + g    ) * SA_STRIDE + k0 + 2 * t + 8];
        const uint32_t a3 = *(const uint32_t*)&sA[(mrow + g + 8) * SA_STRIDE + k0 + 2 * t + 8];
        #pragma unroll
        for (int nc = 0; nc < 4; nc++) {
            const int n = nbase + nc * 8 + g;
            const uint32_t b0 = *(const uint32_t*)&sB[n * SA_STRIDE + k0 + 2 * t];
            const uint32_t b1 = *(const uint32_t*)&sB[n * SA_STRIDE + k0 + 2 * t + 8];
            asm volatile(
                "mma.sync.aligned.m16n8k16.row.col.f32.f16.f16.f32 "
                "{%0,%1,%2,%3}, {%4,%5,%6,%7}, {%8,%9}, {%0,%1,%2,%3};"
                : "+f"(c[nc][0]), "+f"(c[nc][1]), "+f"(c[nc][2]), "+f"(c[nc][3])
                : "r"(a0), "r"(a1), "r"(a2), "r"(a3), "r"(b0), "r"(b1));
        }
    }

    // Bias add + fp16 store to g_h
    const int nodeA = node0 + mrow + g;
    const int nodeB = nodeA + 8;
    #pragma unroll
    for (int nc = 0; nc < 4; nc++) {
        const int col = nbase + nc * 8 + 2 * t;
        const float b0f = sBias[col], b1f = sBias[col + 1];
        const __half2 h0 = __floats2half2_rn(c[nc][0] + b0f, c[nc][1] + b1f);
        const __half2 h1 = __floats2half2_rn(c[nc][2] + b0f, c[nc][3] + b1f);
        if (nodeA < N_NODES) *(__half2*)(g_h + (size_t)nodeA * OUT_F + col) = h0;
        if (nodeB < N_NODES) *(__half2*)(g_h + (size_t)nodeB * OUT_F + col) = h1;
    }
}

// ---------------------------------------------------------------------------
// Scatter (unchanged from the 68.1us best): out[dst] += h[src] * w.
// One edge per HALF-warp; lane16 owns outs lane16*4..+3.
// Gather fp16 (8 B/lane), accumulate fp32 via red.global.add.v4.f32.
// ---------------------------------------------------------------------------
__device__ __forceinline__ void red_add_v4(float* ptr, float4 v) {
    asm volatile("red.global.add.v4.f32 [%0], {%1, %2, %3, %4};"
                 :: "l"(ptr), "f"(v.x), "f"(v.y), "f"(v.z), "f"(v.w)
                 : "memory");
}

__global__ __launch_bounds__(256) void scatter_kernel(
    const int* __restrict__ esrc,
    const int* __restrict__ edst,
    const float* __restrict__ ew,
    float* __restrict__ out)
{
    const int half_id = threadIdx.x >> 4;         // 0..15 within block
    const int lane16  = threadIdx.x & 15;
    const int e = blockIdx.x * 16 + half_id;      // 16 edges per block
    if (e >= N_EDGES) return;

    const int   s = esrc[e];    // broadcast within half-warp
    const int   d = edst[e];
    const float w = ew[e];

    const uint2 hraw = *(const uint2*)(g_h + (size_t)s * OUT_F + lane16 * 4);
    const __half2 h0 = *(const __half2*)&hraw.x;
    const __half2 h1 = *(const __half2*)&hraw.y;
    const float2 f0 = __half22float2(h0);
    const float2 f1 = __half22float2(h1);

    float4 hv = make_float4(f0.x * w, f0.y * w, f1.x * w, f1.y * w);
    red_add_v4(out + (size_t)d * OUT_F + lane16 * 4, hv);
}

// ---------------------------------------------------------------------------
extern "C" void kernel_launch(void* const* d_in, const int* in_sizes, int n_in,
                              void* d_out, int out_size) {
    const float* feat = (const float*)d_in[0];
    const int*   esrc = (const int*)d_in[1];   // int32 (JAX x64 disabled)
    const int*   edst = (const int*)d_in[2];
    const float* ew   = (const float*)d_in[3];
    const float* W    = (const float*)d_in[4];
    const float* b    = (const float*)d_in[5];
    float* out = (float*)d_out;

    gemm_kernel<<<(N_NODES + 63) / 64, 256>>>(feat, W, b, (float4*)out);

    scatter_kernel<<<N_EDGES / 16, 256>>>(esrc, edst, ew, out);
}

// round 8
// speedup vs baseline: 2.3661x; 1.5497x over previous
#include <cuda_runtime.h>
#include <cuda_fp16.h>
#include <stdint.h>

#define N_NODES 50000
#define N_EDGES 800000
#define IN_F    128
#define OUT_F   64

#define SA_STRIDE 136   // halves per smem row (128 + 8 pad -> conflict-free frags)
#define SH_STRIDE 72    // halves per epilogue staging row (64 + 8 pad)

// Scratch (allocation-free rule: __device__ globals)
__device__ __half g_h[(size_t)N_NODES * OUT_F];  // 6.4 MB fp16 h table (L2-resident)

// ---------------------------------------------------------------------------
// GEMM: h = feat @ W^T + b  via mma.sync m16n8k16 (fp16 in, fp32 accum).
// Block: 64 nodes x 64 outs, 256 threads (8 warps).
// Warp w: nodes [(w>>1)*16, +16), outs [(w&1)*32, +32) -> 8 ksteps x 4 nchunks.
// Epilogue stages fragments through smem, then stores g_h with coalesced
// uint4 (fixes the 8-wavefront/instr STG.32 disaster of the previous round).
// Side-job: zero `out` (hidden behind compute).
// ---------------------------------------------------------------------------
__global__ __launch_bounds__(256) void gemm_kernel(
    const float* __restrict__ feat,
    const float* __restrict__ W,
    const float* __restrict__ b,
    float4* __restrict__ out4)
{
    __shared__ __align__(16) __half sA[64 * SA_STRIDE];   // feat tile / epilogue staging
    __shared__ __align__(16) __half sB[64 * SA_STRIDE];   // W [o][k]
    __shared__ float sBias[OUT_F];

    const int tid = threadIdx.x;
    const int node0 = blockIdx.x * 64;

    // Zero the output (independent side-job)
    {
        const int per_blk = (N_NODES * OUT_F / 4 + gridDim.x - 1) / gridDim.x;
        int base = blockIdx.x * per_blk;
        for (int i = tid; i < per_blk; i += 256) {
            int idx = base + i;
            if (idx < N_NODES * OUT_F / 4)
                out4[idx] = make_float4(0.f, 0.f, 0.f, 0.f);
        }
    }

    if (tid < OUT_F) sBias[tid] = b[tid];

    // Load W [64 x 128] fp32 -> fp16 smem (2048 float4, 8 per thread)
    {
        const float4* src = (const float4*)W;
        #pragma unroll
        for (int i = 0; i < 8; i++) {
            int idx = tid + i * 256;
            int o = idx >> 5, c4 = idx & 31;
            float4 v = src[idx];
            __half2 h01 = __floats2half2_rn(v.x, v.y);
            __half2 h23 = __floats2half2_rn(v.z, v.w);
            uint2 pk;
            pk.x = *(const unsigned int*)&h01;
            pk.y = *(const unsigned int*)&h23;
            *(uint2*)&sB[o * SA_STRIDE + c4 * 4] = pk;
        }
    }
    // Load 64 feat rows fp32 -> fp16 smem, zero-pad past N_NODES
    {
        const float4* src = (const float4*)feat;
        #pragma unroll
        for (int i = 0; i < 8; i++) {
            int idx = tid + i * 256;
            int n = idx >> 5, c4 = idx & 31;
            int node = node0 + n;
            float4 v = (node < N_NODES) ? src[(size_t)node * 32 + c4]
                                        : make_float4(0.f, 0.f, 0.f, 0.f);
            __half2 h01 = __floats2half2_rn(v.x, v.y);
            __half2 h23 = __floats2half2_rn(v.z, v.w);
            uint2 pk;
            pk.x = *(const unsigned int*)&h01;
            pk.y = *(const unsigned int*)&h23;
            *(uint2*)&sA[n * SA_STRIDE + c4 * 4] = pk;
        }
    }
    __syncthreads();

    const int lane = tid & 31;
    const int w    = tid >> 5;
    const int g    = lane >> 2;        // groupID (row within 8)
    const int t    = lane & 3;         // thread-in-group (col pair)
    const int mrow = (w >> 1) * 16;    // local node base
    const int nbase = (w & 1) * 32;    // out-column base

    float c[4][4] = {};   // 4 n-chunks x m16n8 fragment

    #pragma unroll
    for (int ks = 0; ks < 8; ks++) {
        const int k0 = ks * 16;
        const uint32_t a0 = *(const uint32_t*)&sA[(mrow + g    ) * SA_STRIDE + k0 + 2 * t];
        const uint32_t a1 = *(const uint32_t*)&sA[(mrow + g + 8) * SA_STRIDE + k0 + 2 * t];
        const uint32_t a2 = *(const uint32_t*)&sA[(mrow + g    ) * SA_STRIDE + k0 + 2 * t + 8];
        const uint32_t a3 = *(const uint32_t*)&sA[(mrow + g + 8) * SA_STRIDE + k0 + 2 * t + 8];
        #pragma unroll
        for (int nc = 0; nc < 4; nc++) {
            const int n = nbase + nc * 8 + g;
            const uint32_t b0 = *(const uint32_t*)&sB[n * SA_STRIDE + k0 + 2 * t];
            const uint32_t b1 = *(const uint32_t*)&sB[n * SA_STRIDE + k0 + 2 * t + 8];
            asm volatile(
                "mma.sync.aligned.m16n8k16.row.col.f32.f16.f16.f32 "
                "{%0,%1,%2,%3}, {%4,%5,%6,%7}, {%8,%9}, {%0,%1,%2,%3};"
                : "+f"(c[nc][0]), "+f"(c[nc][1]), "+f"(c[nc][2]), "+f"(c[nc][3])
                : "r"(a0), "r"(a1), "r"(a2), "r"(a3), "r"(b0), "r"(b1));
        }
    }

    // ---- Epilogue: stage to smem (conflict-free), then coalesced uint4 STG ----
    __syncthreads();                 // everyone done reading sA
    __half* sH = sA;                 // reuse A-tile buffer: 64 rows x SH_STRIDE
    #pragma unroll
    for (int nc = 0; nc < 4; nc++) {
        const int col = nbase + nc * 8 + 2 * t;
        const float b0f = sBias[col], b1f = sBias[col + 1];
        const __half2 h0 = __floats2half2_rn(c[nc][0] + b0f, c[nc][1] + b1f);
        const __half2 h1 = __floats2half2_rn(c[nc][2] + b0f, c[nc][3] + b1f);
        *(__half2*)&sH[(mrow + g    ) * SH_STRIDE + col] = h0;   // bank = 4g+t, distinct
        *(__half2*)&sH[(mrow + g + 8) * SH_STRIDE + col] = h1;
    }
    __syncthreads();
    #pragma unroll
    for (int i = 0; i < 2; i++) {    // 512 uint4 = 64 rows x 128 B
        int idx = tid + i * 256;
        int row = idx >> 3;
        int c16 = idx & 7;
        int node = node0 + row;
        if (node < N_NODES) {
            uint4 v = *(const uint4*)&sH[row * SH_STRIDE + c16 * 8];
            *(uint4*)(g_h + (size_t)node * OUT_F + c16 * 8) = v;   // warp = 4 full lines
        }
    }
}

// ---------------------------------------------------------------------------
// Scatter (unchanged from the 68.1us best): out[dst] += h[src] * w.
// One edge per HALF-warp; lane16 owns outs lane16*4..+3.
// Gather fp16 (8 B/lane), accumulate fp32 via red.global.add.v4.f32.
// ---------------------------------------------------------------------------
__device__ __forceinline__ void red_add_v4(float* ptr, float4 v) {
    asm volatile("red.global.add.v4.f32 [%0], {%1, %2, %3, %4};"
                 :: "l"(ptr), "f"(v.x), "f"(v.y), "f"(v.z), "f"(v.w)
                 : "memory");
}

__global__ __launch_bounds__(256) void scatter_kernel(
    const int* __restrict__ esrc,
    const int* __restrict__ edst,
    const float* __restrict__ ew,
    float* __restrict__ out)
{
    const int half_id = threadIdx.x >> 4;         // 0..15 within block
    const int lane16  = threadIdx.x & 15;
    const int e = blockIdx.x * 16 + half_id;      // 16 edges per block
    if (e >= N_EDGES) return;

    const int   s = esrc[e];    // broadcast within half-warp
    const int   d = edst[e];
    const float w = ew[e];

    const uint2 hraw = *(const uint2*)(g_h + (size_t)s * OUT_F + lane16 * 4);
    const __half2 h0 = *(const __half2*)&hraw.x;
    const __half2 h1 = *(const __half2*)&hraw.y;
    const float2 f0 = __half22float2(h0);
    const float2 f1 = __half22float2(h1);

    float4 hv = make_float4(f0.x * w, f0.y * w, f1.x * w, f1.y * w);
    red_add_v4(out + (size_t)d * OUT_F + lane16 * 4, hv);
}

// ---------------------------------------------------------------------------
extern "C" void kernel_launch(void* const* d_in, const int* in_sizes, int n_in,
                              void* d_out, int out_size) {
    const float* feat = (const float*)d_in[0];
    const int*   esrc = (const int*)d_in[1];   // int32 (JAX x64 disabled)
    const int*   edst = (const int*)d_in[2];
    const float* ew   = (const float*)d_in[3];
    const float* W    = (const float*)d_in[4];
    const float* b    = (const float*)d_in[5];
    float* out = (float*)d_out;

    gemm_kernel<<<(N_NODES + 63) / 64, 256>>>(feat, W, b, (float4*)out);

    scatter_kernel<<<N_EDGES / 16, 256>>>(esrc, edst, ew, out);
}

// round 9
// speedup vs baseline: 2.5124x; 1.0619x over previous
#include <cuda_runtime.h>
#include <cuda_fp16.h>
#include <stdint.h>

#define N_NODES 50000
#define N_EDGES 800000
#define IN_F    128
#define OUT_F   64

#define SA_STRIDE 136   // halves per smem row (128 + 8 pad -> conflict-free frags)
#define SH_STRIDE 72    // halves per epilogue staging row (64 + 8 pad)

// Scratch (allocation-free rule: __device__ globals)
__device__ __half g_h[(size_t)N_NODES * OUT_F];  // 6.4 MB fp16 h table (L2-resident)

// ---------------------------------------------------------------------------
// GEMM: h = feat @ W^T + b  via mma.sync m16n8k16 (fp16 in, fp32 accum).
// (unchanged from the 50.5us round — smem-staged coalesced epilogue)
// Side-job: zero `out`.
// ---------------------------------------------------------------------------
__global__ __launch_bounds__(256) void gemm_kernel(
    const float* __restrict__ feat,
    const float* __restrict__ W,
    const float* __restrict__ b,
    float4* __restrict__ out4)
{
    __shared__ __align__(16) __half sA[64 * SA_STRIDE];   // feat tile / epilogue staging
    __shared__ __align__(16) __half sB[64 * SA_STRIDE];   // W [o][k]
    __shared__ float sBias[OUT_F];

    const int tid = threadIdx.x;
    const int node0 = blockIdx.x * 64;

    // Zero the output (independent side-job)
    {
        const int per_blk = (N_NODES * OUT_F / 4 + gridDim.x - 1) / gridDim.x;
        int base = blockIdx.x * per_blk;
        for (int i = tid; i < per_blk; i += 256) {
            int idx = base + i;
            if (idx < N_NODES * OUT_F / 4)
                out4[idx] = make_float4(0.f, 0.f, 0.f, 0.f);
        }
    }

    if (tid < OUT_F) sBias[tid] = b[tid];

    // Load W [64 x 128] fp32 -> fp16 smem
    {
        const float4* src = (const float4*)W;
        #pragma unroll
        for (int i = 0; i < 8; i++) {
            int idx = tid + i * 256;
            int o = idx >> 5, c4 = idx & 31;
            float4 v = src[idx];
            __half2 h01 = __floats2half2_rn(v.x, v.y);
            __half2 h23 = __floats2half2_rn(v.z, v.w);
            uint2 pk;
            pk.x = *(const unsigned int*)&h01;
            pk.y = *(const unsigned int*)&h23;
            *(uint2*)&sB[o * SA_STRIDE + c4 * 4] = pk;
        }
    }
    // Load 64 feat rows fp32 -> fp16 smem, zero-pad past N_NODES
    {
        const float4* src = (const float4*)feat;
        #pragma unroll
        for (int i = 0; i < 8; i++) {
            int idx = tid + i * 256;
            int n = idx >> 5, c4 = idx & 31;
            int node = node0 + n;
            float4 v = (node < N_NODES) ? src[(size_t)node * 32 + c4]
                                        : make_float4(0.f, 0.f, 0.f, 0.f);
            __half2 h01 = __floats2half2_rn(v.x, v.y);
            __half2 h23 = __floats2half2_rn(v.z, v.w);
            uint2 pk;
            pk.x = *(const unsigned int*)&h01;
            pk.y = *(const unsigned int*)&h23;
            *(uint2*)&sA[n * SA_STRIDE + c4 * 4] = pk;
        }
    }
    __syncthreads();

    const int lane = tid & 31;
    const int w    = tid >> 5;
    const int g    = lane >> 2;
    const int t    = lane & 3;
    const int mrow = (w >> 1) * 16;
    const int nbase = (w & 1) * 32;

    float c[4][4] = {};

    #pragma unroll
    for (int ks = 0; ks < 8; ks++) {
        const int k0 = ks * 16;
        const uint32_t a0 = *(const uint32_t*)&sA[(mrow + g    ) * SA_STRIDE + k0 + 2 * t];
        const uint32_t a1 = *(const uint32_t*)&sA[(mrow + g + 8) * SA_STRIDE + k0 + 2 * t];
        const uint32_t a2 = *(const uint32_t*)&sA[(mrow + g    ) * SA_STRIDE + k0 + 2 * t + 8];
        const uint32_t a3 = *(const uint32_t*)&sA[(mrow + g + 8) * SA_STRIDE + k0 + 2 * t + 8];
        #pragma unroll
        for (int nc = 0; nc < 4; nc++) {
            const int n = nbase + nc * 8 + g;
            const uint32_t b0 = *(const uint32_t*)&sB[n * SA_STRIDE + k0 + 2 * t];
            const uint32_t b1 = *(const uint32_t*)&sB[n * SA_STRIDE + k0 + 2 * t + 8];
            asm volatile(
                "mma.sync.aligned.m16n8k16.row.col.f32.f16.f16.f32 "
                "{%0,%1,%2,%3}, {%4,%5,%6,%7}, {%8,%9}, {%0,%1,%2,%3};"
                : "+f"(c[nc][0]), "+f"(c[nc][1]), "+f"(c[nc][2]), "+f"(c[nc][3])
                : "r"(a0), "r"(a1), "r"(a2), "r"(a3), "r"(b0), "r"(b1));
        }
    }

    // Epilogue: stage to smem (conflict-free), then coalesced uint4 STG
    __syncthreads();
    __half* sH = sA;
    #pragma unroll
    for (int nc = 0; nc < 4; nc++) {
        const int col = nbase + nc * 8 + 2 * t;
        const float b0f = sBias[col], b1f = sBias[col + 1];
        const __half2 h0 = __floats2half2_rn(c[nc][0] + b0f, c[nc][1] + b1f);
        const __half2 h1 = __floats2half2_rn(c[nc][2] + b0f, c[nc][3] + b1f);
        *(__half2*)&sH[(mrow + g    ) * SH_STRIDE + col] = h0;
        *(__half2*)&sH[(mrow + g + 8) * SH_STRIDE + col] = h1;
    }
    __syncthreads();
    #pragma unroll
    for (int i = 0; i < 2; i++) {
        int idx = tid + i * 256;
        int row = idx >> 3;
        int c16 = idx & 7;
        int node = node0 + row;
        if (node < N_NODES) {
            uint4 v = *(const uint4*)&sH[row * SH_STRIDE + c16 * 8];
            *(uint4*)(g_h + (size_t)node * OUT_F + c16 * 8) = v;
        }
    }
}

// ---------------------------------------------------------------------------
// Scatter v2: out[dst] += h[src] * w  via cp.reduce.async.bulk (TMA reduce).
// Block = 64 edges. Half-warps gather fp16 h, scale, stage fp32 rows in smem;
// then 64 threads each issue ONE 256 B bulk atomic-add. 800k TMA ops replace
// 12.8M REDG.128 ops (16x fewer atomic instructions).
// ---------------------------------------------------------------------------
__global__ __launch_bounds__(256) void scatter_kernel(
    const int* __restrict__ esrc,
    const int* __restrict__ edst,
    const float* __restrict__ ew,
    float* __restrict__ out)
{
    __shared__ __align__(16) float sm[64 * OUT_F];   // 16 KB: 64 edge rows

    const int tid = threadIdx.x;
    const int half_id = tid >> 4;     // 0..15
    const int lane16  = tid & 15;
    const int e0 = blockIdx.x * 64;

    // Gather + scale: each half-warp handles 4 edges (rows p*16 + half_id).
    // A warp's two half-warps write adjacent 256 B rows -> conflict-free STS.128.
    #pragma unroll
    for (int p = 0; p < 4; p++) {
        const int r = p * 16 + half_id;       // row in block / edge offset
        const int e = e0 + r;                 // N_EDGES % 64 == 0, no tail
        const int   s = esrc[e];              // broadcast within half-warp
        const float w = ew[e];

        const uint2 hraw = *(const uint2*)(g_h + (size_t)s * OUT_F + lane16 * 4);
        const float2 f0 = __half22float2(*(const __half2*)&hraw.x);
        const float2 f1 = __half22float2(*(const __half2*)&hraw.y);
        float4 hv = make_float4(f0.x * w, f0.y * w, f1.x * w, f1.y * w);
        *(float4*)&sm[r * OUT_F + lane16 * 4] = hv;
    }
    __syncthreads();

    // Issue one bulk atomic-add per edge row (threads 0..63).
    if (tid < 64) {
        asm volatile("fence.proxy.async.shared::cta;" ::: "memory");
        const int d = edst[e0 + tid];
        float* dst = out + (size_t)d * OUT_F;          // 256 B aligned
        uint32_t src_smem;
        asm("{ .reg .u64 t; cvta.to.shared.u64 t, %1; cvt.u32.u64 %0, t; }"
            : "=r"(src_smem) : "l"(&sm[tid * OUT_F]));
        asm volatile(
            "cp.reduce.async.bulk.global.shared::cta.bulk_group.add.f32 "
            "[%0], [%1], %2;"
            :: "l"(dst), "r"(src_smem), "n"(OUT_F * 4)
            : "memory");
        asm volatile("cp.async.bulk.commit_group;" ::: "memory");
        asm volatile("cp.async.bulk.wait_group 0;" ::: "memory");
    }
}

// ---------------------------------------------------------------------------
extern "C" void kernel_launch(void* const* d_in, const int* in_sizes, int n_in,
                              void* d_out, int out_size) {
    const float* feat = (const float*)d_in[0];
    const int*   esrc = (const int*)d_in[1];   // int32 (JAX x64 disabled)
    const int*   edst = (const int*)d_in[2];
    const float* ew   = (const float*)d_in[3];
    const float* W    = (const float*)d_in[4];
    const float* b    = (const float*)d_in[5];
    float* out = (float*)d_out;

    gemm_kernel<<<(N_NODES + 63) / 64, 256>>>(feat, W, b, (float4*)out);

    scatter_kernel<<<N_EDGES / 64, 256>>>(esrc, edst, ew, out);   // 12500 blocks
}